// round 1
// baseline (speedup 1.0000x reference)
#include <cuda_runtime.h>
#include <math.h>

// Problem constants
#define BB   32
#define TT   2000
#define FIN  256
#define HH   1024
#define OO   256
#define NK   1280          // HH + FIN
#define NCTA 143           // ceil(1280/9)
#define TJ   9             // output columns per CTA (143*9 = 1287 >= 1280)
#define NW   8             // warps per CTA
#define KCH  (NK / NW)     // 160 K-elements per warp
#define PACKW 12           // padded row width of packed W (48B, float4-aligned)

// -------- persistent device state (static globals: no allocation) --------
__device__ float    g_wpack[(size_t)NCTA * NK * PACKW]; // ~9.1 MB packed weights
__device__ float    g_wowf[(size_t)HH * HH];            // Wo @ Wf (4 MB)
__device__ float    g_addT[(size_t)NK * BB];            // additive term, [j][b]
__device__ float    g_xiT [(size_t)HH * BB];            // xi_hidden transposed [j][b]
__device__ float    g_u   [(size_t)HH * BB];            // state u, [j][b]
__device__ float    g_v   [2][(size_t)NK * BB];         // double-buffered input vec [k][b]
__device__ unsigned g_count;
__device__ unsigned g_gen;

// -------- precompute 1: WoWf = Wo(1024x256) @ Wf(256x1024) --------
__global__ void k_wowf(const float* __restrict__ Wo, const float* __restrict__ Wf)
{
    __shared__ float sWf[256][32];
    const int bx = blockIdx.x, by = blockIdx.y;
    const int tx = threadIdx.x & 31, ty = threadIdx.x >> 5;   // ty in 0..7

    for (int idx = threadIdx.x; idx < 256 * 32; idx += 256) {
        int o = idx >> 5, c = idx & 31;
        sWf[o][c] = Wf[(size_t)o * HH + bx * 32 + c];
    }
    __syncthreads();

    float acc0 = 0.f, acc1 = 0.f, acc2 = 0.f, acc3 = 0.f;
    const int row0 = by * 32 + ty;
    #pragma unroll 4
    for (int o = 0; o < 256; ++o) {
        float wf = sWf[o][tx];
        acc0 += Wo[(size_t)(row0      ) * OO + o] * wf;
        acc1 += Wo[(size_t)(row0 +  8 ) * OO + o] * wf;
        acc2 += Wo[(size_t)(row0 + 16 ) * OO + o] * wf;
        acc3 += Wo[(size_t)(row0 + 24 ) * OO + o] * wf;
    }
    const int col = bx * 32 + tx;
    g_wowf[(size_t)(row0      ) * HH + col] = acc0;
    g_wowf[(size_t)(row0 +  8 ) * HH + col] = acc1;
    g_wowf[(size_t)(row0 + 16 ) * HH + col] = acc2;
    g_wowf[(size_t)(row0 + 24 ) * HH + col] = acc3;
}

// -------- precompute 2: pack W_big into per-CTA 48B-aligned rows --------
// W_big[k][j]:
//   k<H,  j<H : 1.2*Wr[k][j] + WoWf[k][j]
//   k<H,  j>=H: Wo[k][j-H]
//   k>=H, j<H : Wi[k-H][j]
//   k>=H, j>=H: 0
__global__ void k_pack(const float* __restrict__ Wr, const float* __restrict__ Wi,
                       const float* __restrict__ Wo)
{
    const size_t total = (size_t)NCTA * NK * PACKW;
    size_t idx = (size_t)blockIdx.x * blockDim.x + threadIdx.x;
    if (idx >= total) return;
    int jj  = (int)(idx % PACKW);
    size_t r = idx / PACKW;
    int k   = (int)(r % NK);
    int cta = (int)(r / NK);
    int j   = cta * TJ + jj;

    float val = 0.f;
    if (jj < TJ && j < NK) {
        if (k < HH) {
            if (j < HH) val = 1.2f * Wr[(size_t)k * HH + j] + g_wowf[(size_t)k * HH + j];
            else        val = Wo[(size_t)k * OO + (j - HH)];
        } else {
            if (j < HH) val = Wi[(size_t)(k - HH) * HH + j];
        }
    }
    g_wpack[idx] = val;
}

// -------- precompute 3: addT, xiT, u=0, v0, barrier reset --------
__global__ void k_prep(const float* __restrict__ Wf, const float* __restrict__ xi_h,
                       const float* __restrict__ xi_o, const float* __restrict__ inputs)
{
    int idx = blockIdx.x * blockDim.x + threadIdx.x;      // over NK*BB
    if (idx >= NK * BB) return;
    int b = idx / NK;
    int j = idx % NK;                                     // j fast -> coalesced Wf reads

    float a;
    if (j < HH) {
        float s = 0.f;
        #pragma unroll 4
        for (int o = 0; o < OO; ++o)
            s += xi_o[(size_t)b * OO + o] * Wf[(size_t)o * HH + j];
        a = s;
        float xh = xi_h[(size_t)b * HH + j];
        g_xiT[(size_t)j * BB + b] = xh;
        g_u  [(size_t)j * BB + b] = 0.f;
        g_v[0][(size_t)j * BB + b] = xh;                  // r0 = tanh(0) + xi_h
    } else {
        a = xi_o[(size_t)b * OO + (j - HH)];
        g_v[0][(size_t)j * BB + b] = inputs[(size_t)b * TT * FIN + (j - HH)]; // x_0
    }
    g_addT[(size_t)j * BB + b] = a;
    if (idx == 0) { g_count = 0u; g_gen = 0u; }
}

// -------- grid barrier (monotonic count, acq_rel) --------
__device__ __forceinline__ void grid_barrier(unsigned target)
{
    __syncthreads();
    if (threadIdx.x == 0) {
        unsigned prev;
        asm volatile("atom.acq_rel.gpu.global.add.u32 %0, [%1], 1;"
                     : "=r"(prev) : "l"(&g_count) : "memory");
        if (prev == target * NCTA - 1u) {
            asm volatile("st.release.gpu.global.u32 [%0], %1;"
                         :: "l"(&g_gen), "r"(target) : "memory");
        } else {
            unsigned g;
            do {
                asm volatile("ld.acquire.gpu.global.u32 %0, [%1];"
                             : "=r"(g) : "l"(&g_gen) : "memory");
            } while (g < target);
        }
    }
    __syncthreads();
}

// -------- main persistent kernel: 2000 steps, one barrier each --------
__global__ void __launch_bounds__(256, 1)
k_main(const float* __restrict__ inputs, float* __restrict__ out)
{
    __shared__ float sred[NW][TJ][BB];   // 36 KB cross-warp partials

    const int cta  = blockIdx.x;
    const int w    = threadIdx.x >> 5;
    const int lane = threadIdx.x & 31;
    const int j0   = cta * TJ;

    const float* wp_base = g_wpack + ((size_t)cta * NK + (size_t)w * KCH) * PACKW;

    // static epilogue slot assignment: idx = tid + 256*s over 0..287
    int  e_j[2], e_b[2];
    bool e_valid[2];
    #pragma unroll
    for (int s = 0; s < 2; ++s) {
        int idx = threadIdx.x + 256 * s;
        int jj  = idx >> 5, b = idx & 31;
        int j   = j0 + jj;
        e_valid[s] = (idx < TJ * BB) && (j < NK);
        e_j[s] = j; e_b[s] = b;
    }

    for (int t = 0; t < TT; ++t) {
        const float* vc = g_v[t & 1] + (size_t)(w * KCH) * BB + lane;
        float*       vn = g_v[(t + 1) & 1];

        // prefetch next-step x for the z-column owners (hidden behind the GEMM)
        float xv[2] = {0.f, 0.f};
        #pragma unroll
        for (int s = 0; s < 2; ++s) {
            if (e_valid[s] && e_j[s] >= HH && (t + 1) < TT)
                xv[s] = __ldg(&inputs[(size_t)e_b[s] * TT * FIN +
                                      (size_t)(t + 1) * FIN + (e_j[s] - HH)]);
        }

        // K-chunk dot products: v-load coalesced (+streaming), W uniform from L1
        float a0=0.f,a1=0.f,a2=0.f,a3=0.f,a4=0.f,a5=0.f,a6=0.f,a7=0.f,a8=0.f;
        const float4* wp = (const float4*)wp_base;
        #pragma unroll 4
        for (int k = 0; k < KCH; ++k) {
            float  vb = __ldcs(vc + (size_t)k * BB);
            float4 w0 = __ldg(wp + 3 * k);
            float4 w1 = __ldg(wp + 3 * k + 1);
            float  w2 = __ldg((const float*)(wp + 3 * k + 2));
            a0 += vb * w0.x; a1 += vb * w0.y; a2 += vb * w0.z; a3 += vb * w0.w;
            a4 += vb * w1.x; a5 += vb * w1.y; a6 += vb * w1.z; a7 += vb * w1.w;
            a8 += vb * w2;
        }
        sred[w][0][lane] = a0; sred[w][1][lane] = a1; sred[w][2][lane] = a2;
        sred[w][3][lane] = a3; sred[w][4][lane] = a4; sred[w][5][lane] = a5;
        sred[w][6][lane] = a6; sred[w][7][lane] = a7; sred[w][8][lane] = a8;
        __syncthreads();

        // epilogue: reduce over warps, Euler update + tanh, or emit z
        #pragma unroll
        for (int s = 0; s < 2; ++s) {
            if (!e_valid[s]) continue;
            const int j = e_j[s], b = e_b[s], jj = j - j0;
            float sum = 0.f;
            #pragma unroll
            for (int ww = 0; ww < NW; ++ww) sum += sred[ww][jj][b];
            sum += g_addT[(size_t)j * BB + b];
            if (j < HH) {
                float u  = g_u[(size_t)j * BB + b];
                float un = u + 0.1f * (sum - u);           // DT/TAU = 0.1
                g_u[(size_t)j * BB + b] = un;
                vn[(size_t)j * BB + b]  = tanhf(un) + g_xiT[(size_t)j * BB + b];
            } else {
                out[(size_t)b * TT * OO + (size_t)t * OO + (j - HH)] = sum;
                if ((t + 1) < TT) vn[(size_t)j * BB + b] = xv[s];
            }
        }

        grid_barrier((unsigned)(t + 1));
    }
}

extern "C" void kernel_launch(void* const* d_in, const int* in_sizes, int n_in,
                              void* d_out, int out_size)
{
    const float* inputs = (const float*)d_in[0];   // [32,2000,256]
    const float* Wr     = (const float*)d_in[1];   // [1024,1024]
    const float* Wi     = (const float*)d_in[2];   // [256,1024]
    const float* Wf     = (const float*)d_in[3];   // [256,1024]
    const float* Wo     = (const float*)d_in[4];   // [1024,256]
    const float* xi_h   = (const float*)d_in[5];   // [32,1024]
    const float* xi_o   = (const float*)d_in[6];   // [32,256]
    float*       out    = (float*)d_out;           // [32,2000,256]

    (void)in_sizes; (void)n_in; (void)out_size;

    // precompute (runs each replay; deterministic, cheap)
    k_wowf<<<dim3(32, 32), 256>>>(Wo, Wf);
    {
        size_t total = (size_t)NCTA * NK * PACKW;
        int blocks = (int)((total + 255) / 256);
        k_pack<<<blocks, 256>>>(Wr, Wi, Wo);
    }
    k_prep<<<(NK * BB + 255) / 256, 256>>>(Wf, xi_h, xi_o, inputs);

    // persistent time loop
    k_main<<<NCTA, 256>>>(inputs, out);
}